// round 15
// baseline (speedup 1.0000x reference)
#include <cuda_runtime.h>
#include <math.h>

#define BB 64
#define DD 256
#define LL 2048
#define HH 512
#define KC 128

// ---------------- scratch (device globals: allocation-free) ----------------
__device__ float g_v [BB * DD * LL];   // current v (B, D, L)
__device__ float g_h [BB * DD * LL];   // LN output (tf32-rounded) (B, D, L)
__device__ float g_h1[BB * HH * LL];   // FFN inner (tf32-rounded) (B, H, L)
__device__ float g_stat[BB * 2 * DD];  // [mu over L | sd over L]
__device__ float g_q   [BB * KC];
__device__ float g_qk  [BB * DD];      // scale * wk^T @ q  (per-batch D-vector)
__device__ float g_wsm [BB * LL];      // scores -> softmax weights
__device__ float g_am  [BB * DD];      // att_mean
__device__ float g_as  [BB * DD];      // att_std
__device__ float g_qadd[BB * DD];      // fcq_w @ att_mean
__device__ float g_skip[BB * DD];      // skip_sum accumulator
// tf32-rounded weight copies
__device__ float g_w1[2 * HH * DD];
__device__ float g_w2[2 * DD * HH];

__device__ __forceinline__ float tf32r(float x) {
    float y;
    asm("cvt.rna.tf32.f32 %0, %1;" : "=f"(y) : "f"(x));
    return y;
}

// ---------------- one-time weight rounding ----------------
__global__ void prep_kernel(const float* __restrict__ w1,
                            const float* __restrict__ w2) {
    const int NW1 = 2 * HH * DD, NW2 = 2 * DD * HH;
    int i = blockIdx.x * 256 + threadIdx.x;
    int stride = gridDim.x * 256;
    for (int p = i; p < NW1; p += stride) g_w1[p] = tf32r(w1[p]);
    for (int p = i; p < NW2; p += stride) g_w2[p] = tf32r(w2[p]);
}

// ---------------- LayerNorm over channel dim (att path): src -> g_h --------
__global__ void att_ln_kernel(const float* __restrict__ src,
                              const float* __restrict__ gam,
                              const float* __restrict__ bet) {
    __shared__ float sg[DD], sb[DD];
    int t = threadIdx.x;
    sg[t] = gam[t]; sb[t] = bet[t];
    __syncthreads();
    int p = blockIdx.x * 256 + t;
    int b = p / LL, l = p % LL;
    const float* base = src + (size_t)b * DD * LL + l;
    float s = 0.f, s2 = 0.f;
    #pragma unroll 8
    for (int d = 0; d < DD; d++) {
        float x = base[(size_t)d * LL];
        s += x; s2 += x * x;
    }
    float mu = s * (1.f / DD);
    float var = s2 * (1.f / DD) - mu * mu;
    float rs = rsqrtf(var + 1e-6f);
    float* out = g_h + (size_t)b * DD * LL + l;
    #pragma unroll 8
    for (int d = 0; d < DD; d++) {
        float x = base[(size_t)d * LL];
        out[(size_t)d * LL] = tf32r((x - mu) * rs * sg[d] + sb[d]);
    }
}

// ---- FFN LN: reads src+qadd, writes LN(f_in) into g_h ONLY (f_in is
//      recomputed by the w2-GEMM epilogue as vsrc + qadd) ------------------
__global__ void ffn_ln_kernel(const float* __restrict__ src,
                              const float* __restrict__ gam,
                              const float* __restrict__ bet) {
    __shared__ float sg[DD], sb[DD], sq[DD];
    int t = threadIdx.x;
    int b = (blockIdx.x * 256) / LL;
    sg[t] = gam[t]; sb[t] = bet[t]; sq[t] = g_qadd[b * DD + t];
    __syncthreads();
    int p = blockIdx.x * 256 + t;
    int l = p % LL;
    const float* base = src + (size_t)b * DD * LL + l;
    float s = 0.f, s2 = 0.f;
    #pragma unroll 8
    for (int d = 0; d < DD; d++) {
        float x = base[(size_t)d * LL] + sq[d];
        s += x; s2 += x * x;
    }
    float mu = s * (1.f / DD);
    float var = s2 * (1.f / DD) - mu * mu;
    float rs = rsqrtf(var + 1e-6f);
    float* out = g_h + (size_t)b * DD * LL + l;
    #pragma unroll 8
    for (int d = 0; d < DD; d++) {
        float x = base[(size_t)d * LL] + sq[d];
        out[(size_t)d * LL] = tf32r((x - mu) * rs * sg[d] + sb[d]);
    }
}

// ---------------- per (b,d) mean/sd over L of g_h -> g_stat ----------------
__global__ void colstats_kernel() {
    int row = blockIdx.x;            // b*DD + d
    int b = row / DD, d = row % DD;
    const float* src = g_h + (size_t)row * LL;
    float s = 0.f, s2 = 0.f;
    for (int l = threadIdx.x; l < LL; l += 256) {
        float x = src[l];
        s += x; s2 += x * x;
    }
    __shared__ float r1[256], r2[256];
    r1[threadIdx.x] = s; r2[threadIdx.x] = s2;
    __syncthreads();
    for (int o = 128; o > 0; o >>= 1) {
        if (threadIdx.x < o) { r1[threadIdx.x] += r1[threadIdx.x + o]; r2[threadIdx.x] += r2[threadIdx.x + o]; }
        __syncthreads();
    }
    if (threadIdx.x == 0) {
        float mu = r1[0] * (1.f / LL);
        float var = r2[0] * (1.f / LL) - mu * mu;
        var = fmaxf(var, 1e-10f);
        g_stat[b * 2 * DD + d]      = mu;
        g_stat[b * 2 * DD + DD + d] = sqrtf(var);
    }
}

// ---------------- q = concat(mu,sd) @ wq^T : warp-per-output ---------------
__global__ void q_kernel(const float* __restrict__ wq) {
    int b = blockIdx.x;
    int warp = threadIdx.x >> 5, lane = threadIdx.x & 31;
    __shared__ float st[2 * DD];
    for (int e = threadIdx.x; e < 2 * DD; e += 512) st[e] = g_stat[b * 2 * DD + e];
    __syncthreads();
    int j = blockIdx.y * 16 + warp;      // 8 y-blocks x 16 warps = 128 outputs
    const float* wr = wq + (size_t)j * 2 * DD;
    float acc = 0.f;
    #pragma unroll
    for (int e = lane; e < 2 * DD; e += 32) acc += wr[e] * st[e];
    #pragma unroll
    for (int o = 16; o > 0; o >>= 1) acc += __shfl_xor_sync(0xffffffffu, acc, o);
    if (lane == 0) g_q[b * KC + j] = acc;
}

// ------- qk[b,d] = scale * sum_k wk[k,d] * q[b,k]  (k-GEMM eliminated) -----
__global__ void qk_kernel(const float* __restrict__ wk) {
    int b = blockIdx.x;
    int d = blockIdx.y * 128 + threadIdx.x;   // 2 y-blocks x 128 threads
    __shared__ float qs[KC];
    if (threadIdx.x < KC) qs[threadIdx.x] = g_q[b * KC + threadIdx.x];
    __syncthreads();
    float acc = 0.f;
    #pragma unroll 8
    for (int k = 0; k < KC; k++) acc += wk[(size_t)k * DD + d] * qs[k];
    g_qk[b * DD + d] = acc * 0.08838834764831845f;  // 1/sqrt(128)
}

// ------- scores: g_wsm[b,l] = qk . vt_l  (vt = g_h); DRAM-parallel ---------
__global__ void score_kernel() {
    int b = blockIdx.x;
    int l = blockIdx.y * 256 + threadIdx.x;   // 8 y-blocks x 256 threads
    __shared__ float qsh[DD];
    qsh[threadIdx.x] = g_qk[b * DD + threadIdx.x];
    __syncthreads();
    const float* hb = g_h + (size_t)b * DD * LL + l;
    float acc = 0.f;
    #pragma unroll 8
    for (int d = 0; d < DD; d++) acc += hb[(size_t)d * LL] * qsh[d];
    g_wsm[b * LL + l] = acc;
}

// ------- softmax finish over L (in-place on g_wsm, 8 MB only) --------------
__global__ void softmax_fin() {
    int b = blockIdx.x, t = threadIdx.x;   // 1024 threads, 2 elems each
    __shared__ float red[1024];
    float* wb = g_wsm + b * LL;
    float v0 = wb[t], v1 = wb[t + 1024];
    red[t] = fmaxf(v0, v1);
    __syncthreads();
    for (int o = 512; o > 0; o >>= 1) {
        if (t < o) red[t] = fmaxf(red[t], red[t + o]);
        __syncthreads();
    }
    float m = red[0];
    __syncthreads();
    float e0 = expf(v0 - m), e1 = expf(v1 - m);
    red[t] = e0 + e1;
    __syncthreads();
    for (int o = 512; o > 0; o >>= 1) {
        if (t < o) red[t] += red[t + o];
        __syncthreads();
    }
    float inv = 1.f / red[0];
    wb[t] = e0 * inv;
    wb[t + 1024] = e1 * inv;
}

// ---------------- weighted mean/std over L : g_h,g_wsm -> g_am,g_as --------
__global__ void att_kernel() {
    int row = blockIdx.x;            // b*DD + d
    int b = row / DD;
    const float* src = g_h + (size_t)row * LL;
    const float* w = g_wsm + b * LL;
    float s1 = 0.f, s2 = 0.f;
    for (int l = threadIdx.x; l < LL; l += 256) {
        float x = src[l], ww = w[l];
        s1 += x * ww; s2 += x * x * ww;
    }
    __shared__ float r1[256], r2[256];
    r1[threadIdx.x] = s1; r2[threadIdx.x] = s2;
    __syncthreads();
    for (int o = 128; o > 0; o >>= 1) {
        if (threadIdx.x < o) { r1[threadIdx.x] += r1[threadIdx.x + o]; r2[threadIdx.x] += r2[threadIdx.x + o]; }
        __syncthreads();
    }
    if (threadIdx.x == 0) {
        float mean = r1[0];
        float var = fmaxf(r2[0] - mean * mean, 1e-10f);
        g_am[row] = mean;
        g_as[row] = sqrtf(var);
    }
}

// ---------------- skip accumulate + qadd : warp-per-output -----------------
__global__ void skip_kernel(const float* __restrict__ fc_w,
                            const float* __restrict__ fc_b,
                            const float* __restrict__ fcq_w,
                            int first) {
    int b = blockIdx.x;
    int warp = threadIdx.x >> 5, lane = threadIdx.x & 31;
    __shared__ float sm[DD], ss[DD];
    sm[threadIdx.x] = g_am[b * DD + threadIdx.x];
    ss[threadIdx.x] = g_as[b * DD + threadIdx.x];
    __syncthreads();
    int o = blockIdx.y * 64 + warp * 8;  // 4 y-blocks x 8 warps x 8 outputs
    for (int oo = o; oo < o + 8; oo++) {
        const float* fr = fc_w + (size_t)oo * 2 * DD;
        const float* qr = fcq_w + (size_t)oo * DD;
        float accs = 0.f, accq = 0.f;
        #pragma unroll
        for (int d = lane; d < DD; d += 32) {
            accs += fr[d] * sm[d] + fr[DD + d] * ss[d];
            accq += qr[d] * sm[d];
        }
        #pragma unroll
        for (int sh = 16; sh > 0; sh >>= 1) {
            accs += __shfl_xor_sync(0xffffffffu, accs, sh);
            accq += __shfl_xor_sync(0xffffffffu, accq, sh);
        }
        if (lane == 0) {
            float prev = first ? 0.f : g_skip[b * DD + oo];
            g_skip[b * DD + oo] = prev + accs + fc_b[oo];
            g_qadd[b * DD + oo] = accq;
        }
    }
}

// ---------------- tf32 tensor-core batched GEMM, cp.async pipelined --------
// R14 winner + BK=32: CTA tile 128x128x32, 4 warps, warp tile 64x64 via
// 4x8 m16n8k8 (4 kk-halves/iter), 3 stages (107.5KB), 2 CTAs/SM.
// A-fragments via ldmatrix.m8n8.x4.b16 (stride 36: 144*r mod 128 = 16r,
// conflict-free). B scalar LDS, stride 136 (8k+c covers all banks).
// ADDQ: epilogue adds qadd[row] broadcast (f_in = Cin + qadd inline).
// NOFF: n-tile offset for L2-chunked launches (h1 chunk stays L2-resident).
#define GSTAGES 3
#define AS_FLOATS 4608            /* 128*36 */
#define BS_FLOATS 4352            /* 32*136 */
#define STG_FLOATS (AS_FLOATS + BS_FLOATS)
#define GEMM_SMEM (GSTAGES * STG_FLOATS * 4)

__device__ __forceinline__ void cp16(unsigned dst, const float* src) {
    asm volatile("cp.async.cg.shared.global [%0], [%1], 16;" :: "r"(dst), "l"(src));
}

template<int M_, int K_, bool RELU, bool ADDIN, bool BIAS, bool TF32OUT, bool ADDQ>
__global__ void __launch_bounds__(128, 2)
gemm_tc(const float* __restrict__ A,
        const float* __restrict__ Bm,
        const float* __restrict__ bias,
        const float* __restrict__ Cin,
        float* __restrict__ C,
        int noff) {
    extern __shared__ float smem[];
    const int b  = blockIdx.z;
    const int m0 = blockIdx.y * 128;
    const int n0 = (blockIdx.x + noff) * 128;
    const int tid  = threadIdx.x;
    const int warp = tid >> 5, lane = tid & 31;
    const int wm = (warp & 1) * 64;    // 0 or 64
    const int wn = (warp >> 1) * 64;   // 0 or 64
    const float* Bbase = Bm + (size_t)b * K_ * LL;

    // A stage-load: rows tid>>3 (+16h, h=0..7), cols (tid&7)*4
    const int ar = tid >> 3;
    const int ac = (tid & 7) * 4;
    // B stage-load: rows tid>>5 (+4h, h=0..7), cols (tid&31)*4
    const int bkr = tid >> 5;
    const int bcb = (tid & 31) * 4;

    const unsigned sbase = (unsigned)__cvta_generic_to_shared(smem);

    // ldmatrix per-thread source offset (floats, stride 36):
    //   matrix = lane>>3: bit0 -> +8 rows, bit1 -> +4 cols
    const int a_mat = lane >> 3;
    const int a_ld_off = (((a_mat & 1) * 8) + (lane & 7)) * 36 + (a_mat >> 1) * 4;

    float c[4][8][4];
    #pragma unroll
    for (int i = 0; i < 4; i++)
        #pragma unroll
        for (int j = 0; j < 8; j++)
            #pragma unroll
            for (int r = 0; r < 4; r++) c[i][j][r] = 0.f;

    const int nIter = K_ / 32;

    auto load_stage = [&](int it, int stg) {
        unsigned abase = sbase + (unsigned)(stg * STG_FLOATS) * 4u;
        unsigned bbase = abase + (unsigned)AS_FLOATS * 4u;
        int k0 = it * 32;
        #pragma unroll
        for (int h = 0; h < 8; h++) {
            int m = ar + h * 16;
            cp16(abase + (unsigned)(m * 36 + ac) * 4u,
                 &A[(size_t)(m0 + m) * K_ + k0 + ac]);
        }
        #pragma unroll
        for (int h = 0; h < 8; h++) {
            int k = bkr + h * 4;
            cp16(bbase + (unsigned)(k * 136 + bcb) * 4u,
                 &Bbase[(size_t)(k0 + k) * LL + n0 + bcb]);
        }
    };

    #pragma unroll
    for (int s = 0; s < GSTAGES - 1; s++) {
        load_stage(s, s);
        asm volatile("cp.async.commit_group;");
    }

    int cur = 0, nxt_stg = GSTAGES - 1;
    for (int i = 0; i < nIter; i++) {
        asm volatile("cp.async.wait_group %0;" :: "n"(GSTAGES - 2));
        __syncthreads();
        int nxt = i + GSTAGES - 1;
        if (nxt < nIter) load_stage(nxt, nxt_stg);
        asm volatile("cp.async.commit_group;");
        if (++nxt_stg == GSTAGES) nxt_stg = 0;

        const unsigned as_u = sbase + (unsigned)(cur * STG_FLOATS) * 4u;
        const float* bs_ = smem + cur * STG_FLOATS + AS_FLOATS;
        if (++cur == GSTAGES) cur = 0;

        #pragma unroll
        for (int kk = 0; kk < 32; kk += 8) {
            unsigned af[4][4], bf[8][2];
            #pragma unroll
            for (int mi = 0; mi < 4; mi++) {
                unsigned aaddr = as_u +
                    (unsigned)((wm + mi * 16) * 36 + kk + a_ld_off) * 4u;
                asm volatile(
                    "ldmatrix.sync.aligned.m8n8.x4.shared.b16 {%0,%1,%2,%3}, [%4];"
                    : "=r"(af[mi][0]), "=r"(af[mi][1]),
                      "=r"(af[mi][2]), "=r"(af[mi][3])
                    : "r"(aaddr));
            }
            #pragma unroll
            for (int ni = 0; ni < 8; ni++) {
                int col = wn + ni * 8 + (lane >> 2);
                int kr = kk + (lane & 3);
                bf[ni][0] = __float_as_uint(bs_[ kr      * 136 + col]);
                bf[ni][1] = __float_as_uint(bs_[(kr + 4) * 136 + col]);
            }
            #pragma unroll
            for (int mi = 0; mi < 4; mi++)
                #pragma unroll
                for (int ni = 0; ni < 8; ni++) {
                    asm volatile(
                        "mma.sync.aligned.m16n8k8.row.col.f32.tf32.tf32.f32 "
                        "{%0,%1,%2,%3}, {%4,%5,%6,%7}, {%8,%9}, {%0,%1,%2,%3};"
                        : "+f"(c[mi][ni][0]), "+f"(c[mi][ni][1]),
                          "+f"(c[mi][ni][2]), "+f"(c[mi][ni][3])
                        : "r"(af[mi][0]), "r"(af[mi][1]), "r"(af[mi][2]), "r"(af[mi][3]),
                          "r"(bf[ni][0]), "r"(bf[ni][1]));
                }
        }
    }

    // ---- epilogue
    const size_t base = (size_t)b * M_ * LL;
    const float* qa = ADDQ ? (g_qadd + b * DD) : nullptr;
    #pragma unroll
    for (int mi = 0; mi < 4; mi++) {
        int row = m0 + wm + mi * 16 + (lane >> 2);
        float bv0 = BIAS ? bias[row] : 0.f;
        float bv1 = BIAS ? bias[row + 8] : 0.f;
        if (ADDQ) { bv0 += qa[row]; bv1 += qa[row + 8]; }
        #pragma unroll
        for (int ni = 0; ni < 8; ni++) {
            int col = n0 + wn + ni * 8 + (lane & 3) * 2;
            float v0 = c[mi][ni][0] + bv0, v1 = c[mi][ni][1] + bv0;
            float v2 = c[mi][ni][2] + bv1, v3 = c[mi][ni][3] + bv1;
            if (RELU) {
                v0 = fmaxf(v0, 0.f); v1 = fmaxf(v1, 0.f);
                v2 = fmaxf(v2, 0.f); v3 = fmaxf(v3, 0.f);
            }
            size_t i0 = base + (size_t)row * LL + col;
            size_t i1 = base + (size_t)(row + 8) * LL + col;
            if (ADDIN) {
                float2 p0 = *(const float2*)&Cin[i0];
                float2 p1 = *(const float2*)&Cin[i1];
                v0 += p0.x; v1 += p0.y; v2 += p1.x; v3 += p1.y;
            }
            if (TF32OUT) {
                v0 = tf32r(v0); v1 = tf32r(v1);
                v2 = tf32r(v2); v3 = tf32r(v3);
            }
            *(float2*)&C[i0] = make_float2(v0, v1);
            *(float2*)&C[i1] = make_float2(v2, v3);
        }
    }
}

// ---------------- final relu + BatchNorm over batch -> out -----------------
__global__ void bn_kernel(float* __restrict__ out) {
    int d = blockIdx.x;        // 0..255
    int b = threadIdx.x;       // 0..63
    __shared__ float r1[64], r2[64];
    float y = fmaxf(g_skip[b * DD + d], 0.f);
    r1[b] = y; r2[b] = y * y;
    __syncthreads();
    for (int o = 32; o > 0; o >>= 1) {
        if (b < o) { r1[b] += r1[b + o]; r2[b] += r2[b + o]; }
        __syncthreads();
    }
    float mu = r1[0] * (1.f / 64.f);
    float var = r2[0] * (1.f / 64.f) - mu * mu;
    float rs = rsqrtf(var + 1e-5f);
    out[b * DD + d] = (y - mu) * rs;
}

// ---------------- launch ----------------
extern "C" void kernel_launch(void* const* d_in, const int* in_sizes, int n_in,
                              void* d_out, int out_size) {
    const float* x      = (const float*)d_in[0];
    const float* wk     = (const float*)d_in[1];
    const float* wq     = (const float*)d_in[2];
    const float* fcq_w  = (const float*)d_in[3];
    const float* fc_w   = (const float*)d_in[4];
    const float* fc_b   = (const float*)d_in[5];
    const float* att_g  = (const float*)d_in[6];
    const float* att_b  = (const float*)d_in[7];
    const float* w1     = (const float*)d_in[8];
    const float* b1     = (const float*)d_in[9];
    const float* w2     = (const float*)d_in[10];
    const float* b2     = (const float*)d_in[11];
    const float* ffw_g  = (const float*)d_in[12];
    const float* ffw_b  = (const float*)d_in[13];
    float* out = (float*)d_out;

    float *p_v, *p_h, *p_h1, *p_w1, *p_w2;
    cudaGetSymbolAddress((void**)&p_v,  g_v);
    cudaGetSymbolAddress((void**)&p_h,  g_h);
    cudaGetSymbolAddress((void**)&p_h1, g_h1);
    cudaGetSymbolAddress((void**)&p_w1, g_w1);
    cudaGetSymbolAddress((void**)&p_w2, g_w2);

    cudaFuncSetAttribute(gemm_tc<HH, DD, true, false, true, true, false>,
                         cudaFuncAttributeMaxDynamicSharedMemorySize, GEMM_SMEM);
    cudaFuncSetAttribute(gemm_tc<DD, HH, false, true, true, false, true>,
                         cudaFuncAttributeMaxDynamicSharedMemorySize, GEMM_SMEM);

    prep_kernel<<<512, 256>>>(w1, w2);

    for (int i = 0; i < 2; i++) {
        const float* vsrc = (i == 0) ? x : (const float*)p_v;
        att_ln_kernel<<<BB * LL / 256, 256>>>(vsrc, att_g + i * DD, att_b + i * DD);
        colstats_kernel<<<BB * DD, 256>>>();
        q_kernel<<<dim3(BB, 8), 512>>>(wq + (size_t)i * KC * 2 * DD);
        qk_kernel<<<dim3(BB, 2), 128>>>(wk + (size_t)i * KC * DD);
        score_kernel<<<dim3(BB, LL / 256), 256>>>();
        softmax_fin<<<BB, 1024>>>();
        att_kernel<<<BB * DD, 256>>>();
        skip_kernel<<<dim3(BB, 4), 256>>>(fc_w + (size_t)i * DD * 2 * DD,
                                          fc_b + (size_t)i * DD,
                                          fcq_w + (size_t)i * DD * DD, i == 0);
        ffn_ln_kernel<<<BB * LL / 256, 256>>>(vsrc, ffw_g + i * DD, ffw_b + i * DD);
        // L2-chunked FFN: per 512-col chunk, h1 (67MB) stays L2-resident
        // between the w1 producer and w2 consumer.
        for (int ch = 0; ch < 4; ch++) {
            // h1 chunk = relu(w1 @ h + b1), tf32-rounded store
            gemm_tc<HH, DD, true, false, true, true, false>
                <<<dim3(4, HH / 128, BB), 128, GEMM_SMEM>>>(
                    p_w1 + (size_t)i * HH * DD, p_h,
                    b1 + (size_t)i * HH, nullptr, p_h1, ch * 4);
            // v chunk = w2 @ h1 + b2 + (vsrc + qadd) -> g_v
            gemm_tc<DD, HH, false, true, true, false, true>
                <<<dim3(4, DD / 128, BB), 128, GEMM_SMEM>>>(
                    p_w2 + (size_t)i * DD * HH, p_h1,
                    b2 + (size_t)i * DD, vsrc, p_v, ch * 4);
        }
    }

    bn_kernel<<<DD, 64>>>(out);
}

// round 17
// speedup vs baseline: 1.0936x; 1.0936x over previous
#include <cuda_runtime.h>
#include <math.h>

#define BB 64
#define DD 256
#define LL 2048
#define HH 512
#define KC 128

// ---------------- scratch (device globals: allocation-free) ----------------
__device__ float g_v [BB * DD * LL];   // current v (B, D, L)
__device__ float g_h [BB * DD * LL];   // LN output (tf32-rounded) (B, D, L)
__device__ float g_h1[BB * HH * LL];   // FFN inner (tf32-rounded) (B, H, L)
__device__ float g_stat[BB * 2 * DD];  // [mu over L | sd over L]
__device__ float g_q   [BB * KC];
__device__ float g_qk  [BB * DD];      // scale * wk^T @ q  (per-batch D-vector)
__device__ float g_wsm [BB * LL];      // scores -> softmax weights
__device__ float g_am  [BB * DD];      // att_mean
__device__ float g_as  [BB * DD];      // att_std
__device__ float g_qadd[BB * DD];      // fcq_w @ att_mean
__device__ float g_skip[BB * DD];      // skip_sum accumulator
// tf32-rounded weight copies
__device__ float g_w1[2 * HH * DD];
__device__ float g_w2[2 * DD * HH];

__device__ __forceinline__ float tf32r(float x) {
    float y;
    asm("cvt.rna.tf32.f32 %0, %1;" : "=f"(y) : "f"(x));
    return y;
}

// ---------------- one-time weight rounding ----------------
__global__ void prep_kernel(const float* __restrict__ w1,
                            const float* __restrict__ w2) {
    const int NW1 = 2 * HH * DD, NW2 = 2 * DD * HH;
    int i = blockIdx.x * 256 + threadIdx.x;
    int stride = gridDim.x * 256;
    for (int p = i; p < NW1; p += stride) g_w1[p] = tf32r(w1[p]);
    for (int p = i; p < NW2; p += stride) g_w2[p] = tf32r(w2[p]);
}

// ---------------- LayerNorm over channel dim (att path): src -> g_h --------
__global__ void att_ln_kernel(const float* __restrict__ src,
                              const float* __restrict__ gam,
                              const float* __restrict__ bet) {
    __shared__ float sg[DD], sb[DD];
    int t = threadIdx.x;
    sg[t] = gam[t]; sb[t] = bet[t];
    __syncthreads();
    int p = blockIdx.x * 256 + t;
    int b = p / LL, l = p % LL;
    const float* base = src + (size_t)b * DD * LL + l;
    float s = 0.f, s2 = 0.f;
    #pragma unroll 8
    for (int d = 0; d < DD; d++) {
        float x = base[(size_t)d * LL];
        s += x; s2 += x * x;
    }
    float mu = s * (1.f / DD);
    float var = s2 * (1.f / DD) - mu * mu;
    float rs = rsqrtf(var + 1e-6f);
    float* out = g_h + (size_t)b * DD * LL + l;
    #pragma unroll 8
    for (int d = 0; d < DD; d++) {
        float x = base[(size_t)d * LL];
        out[(size_t)d * LL] = tf32r((x - mu) * rs * sg[d] + sb[d]);
    }
}

// ---- FFN LN: reads src+qadd, writes LN(f_in) into g_h ONLY (f_in is
//      recomputed by the w2-GEMM epilogue as vsrc + qadd) ------------------
__global__ void ffn_ln_kernel(const float* __restrict__ src,
                              const float* __restrict__ gam,
                              const float* __restrict__ bet) {
    __shared__ float sg[DD], sb[DD], sq[DD];
    int t = threadIdx.x;
    int b = (blockIdx.x * 256) / LL;
    sg[t] = gam[t]; sb[t] = bet[t]; sq[t] = g_qadd[b * DD + t];
    __syncthreads();
    int p = blockIdx.x * 256 + t;
    int l = p % LL;
    const float* base = src + (size_t)b * DD * LL + l;
    float s = 0.f, s2 = 0.f;
    #pragma unroll 8
    for (int d = 0; d < DD; d++) {
        float x = base[(size_t)d * LL] + sq[d];
        s += x; s2 += x * x;
    }
    float mu = s * (1.f / DD);
    float var = s2 * (1.f / DD) - mu * mu;
    float rs = rsqrtf(var + 1e-6f);
    float* out = g_h + (size_t)b * DD * LL + l;
    #pragma unroll 8
    for (int d = 0; d < DD; d++) {
        float x = base[(size_t)d * LL] + sq[d];
        out[(size_t)d * LL] = tf32r((x - mu) * rs * sg[d] + sb[d]);
    }
}

// ---------------- per (b,d) mean/sd over L of g_h -> g_stat ----------------
__global__ void colstats_kernel() {
    int row = blockIdx.x;            // b*DD + d
    int b = row / DD, d = row % DD;
    const float* src = g_h + (size_t)row * LL;
    float s = 0.f, s2 = 0.f;
    for (int l = threadIdx.x; l < LL; l += 256) {
        float x = src[l];
        s += x; s2 += x * x;
    }
    __shared__ float r1[256], r2[256];
    r1[threadIdx.x] = s; r2[threadIdx.x] = s2;
    __syncthreads();
    for (int o = 128; o > 0; o >>= 1) {
        if (threadIdx.x < o) { r1[threadIdx.x] += r1[threadIdx.x + o]; r2[threadIdx.x] += r2[threadIdx.x + o]; }
        __syncthreads();
    }
    if (threadIdx.x == 0) {
        float mu = r1[0] * (1.f / LL);
        float var = r2[0] * (1.f / LL) - mu * mu;
        var = fmaxf(var, 1e-10f);
        g_stat[b * 2 * DD + d]      = mu;
        g_stat[b * 2 * DD + DD + d] = sqrtf(var);
    }
}

// ---------------- q = concat(mu,sd) @ wq^T : warp-per-output ---------------
__global__ void q_kernel(const float* __restrict__ wq) {
    int b = blockIdx.x;
    int warp = threadIdx.x >> 5, lane = threadIdx.x & 31;
    __shared__ float st[2 * DD];
    for (int e = threadIdx.x; e < 2 * DD; e += 512) st[e] = g_stat[b * 2 * DD + e];
    __syncthreads();
    int j = blockIdx.y * 16 + warp;      // 8 y-blocks x 16 warps = 128 outputs
    const float* wr = wq + (size_t)j * 2 * DD;
    float acc = 0.f;
    #pragma unroll
    for (int e = lane; e < 2 * DD; e += 32) acc += wr[e] * st[e];
    #pragma unroll
    for (int o = 16; o > 0; o >>= 1) acc += __shfl_xor_sync(0xffffffffu, acc, o);
    if (lane == 0) g_q[b * KC + j] = acc;
}

// ------- qk[b,d] = scale * sum_k wk[k,d] * q[b,k]  (k-GEMM eliminated) -----
__global__ void qk_kernel(const float* __restrict__ wk) {
    int b = blockIdx.x;
    int d = blockIdx.y * 128 + threadIdx.x;   // 2 y-blocks x 128 threads
    __shared__ float qs[KC];
    if (threadIdx.x < KC) qs[threadIdx.x] = g_q[b * KC + threadIdx.x];
    __syncthreads();
    float acc = 0.f;
    #pragma unroll 8
    for (int k = 0; k < KC; k++) acc += wk[(size_t)k * DD + d] * qs[k];
    g_qk[b * DD + d] = acc * 0.08838834764831845f;  // 1/sqrt(128)
}

// ------- scores: g_wsm[b,l] = qk . vt_l  (vt = g_h); DRAM-parallel ---------
__global__ void score_kernel() {
    int b = blockIdx.x;
    int l = blockIdx.y * 256 + threadIdx.x;   // 8 y-blocks x 256 threads
    __shared__ float qsh[DD];
    qsh[threadIdx.x] = g_qk[b * DD + threadIdx.x];
    __syncthreads();
    const float* hb = g_h + (size_t)b * DD * LL + l;
    float acc = 0.f;
    #pragma unroll 8
    for (int d = 0; d < DD; d++) acc += hb[(size_t)d * LL] * qsh[d];
    g_wsm[b * LL + l] = acc;
}

// ------- softmax finish over L (in-place on g_wsm, 8 MB only) --------------
__global__ void softmax_fin() {
    int b = blockIdx.x, t = threadIdx.x;   // 1024 threads, 2 elems each
    __shared__ float red[1024];
    float* wb = g_wsm + b * LL;
    float v0 = wb[t], v1 = wb[t + 1024];
    red[t] = fmaxf(v0, v1);
    __syncthreads();
    for (int o = 512; o > 0; o >>= 1) {
        if (t < o) red[t] = fmaxf(red[t], red[t + o]);
        __syncthreads();
    }
    float m = red[0];
    __syncthreads();
    float e0 = expf(v0 - m), e1 = expf(v1 - m);
    red[t] = e0 + e1;
    __syncthreads();
    for (int o = 512; o > 0; o >>= 1) {
        if (t < o) red[t] += red[t + o];
        __syncthreads();
    }
    float inv = 1.f / red[0];
    wb[t] = e0 * inv;
    wb[t + 1024] = e1 * inv;
}

// ---------------- weighted mean/std over L : g_h,g_wsm -> g_am,g_as --------
__global__ void att_kernel() {
    int row = blockIdx.x;            // b*DD + d
    int b = row / DD;
    const float* src = g_h + (size_t)row * LL;
    const float* w = g_wsm + b * LL;
    float s1 = 0.f, s2 = 0.f;
    for (int l = threadIdx.x; l < LL; l += 256) {
        float x = src[l], ww = w[l];
        s1 += x * ww; s2 += x * x * ww;
    }
    __shared__ float r1[256], r2[256];
    r1[threadIdx.x] = s1; r2[threadIdx.x] = s2;
    __syncthreads();
    for (int o = 128; o > 0; o >>= 1) {
        if (threadIdx.x < o) { r1[threadIdx.x] += r1[threadIdx.x + o]; r2[threadIdx.x] += r2[threadIdx.x + o]; }
        __syncthreads();
    }
    if (threadIdx.x == 0) {
        float mean = r1[0];
        float var = fmaxf(r2[0] - mean * mean, 1e-10f);
        g_am[row] = mean;
        g_as[row] = sqrtf(var);
    }
}

// ---------------- skip accumulate + qadd : warp-per-output -----------------
__global__ void skip_kernel(const float* __restrict__ fc_w,
                            const float* __restrict__ fc_b,
                            const float* __restrict__ fcq_w,
                            int first) {
    int b = blockIdx.x;
    int warp = threadIdx.x >> 5, lane = threadIdx.x & 31;
    __shared__ float sm[DD], ss[DD];
    sm[threadIdx.x] = g_am[b * DD + threadIdx.x];
    ss[threadIdx.x] = g_as[b * DD + threadIdx.x];
    __syncthreads();
    int o = blockIdx.y * 64 + warp * 8;  // 4 y-blocks x 8 warps x 8 outputs
    for (int oo = o; oo < o + 8; oo++) {
        const float* fr = fc_w + (size_t)oo * 2 * DD;
        const float* qr = fcq_w + (size_t)oo * DD;
        float accs = 0.f, accq = 0.f;
        #pragma unroll
        for (int d = lane; d < DD; d += 32) {
            accs += fr[d] * sm[d] + fr[DD + d] * ss[d];
            accq += qr[d] * sm[d];
        }
        #pragma unroll
        for (int sh = 16; sh > 0; sh >>= 1) {
            accs += __shfl_xor_sync(0xffffffffu, accs, sh);
            accq += __shfl_xor_sync(0xffffffffu, accq, sh);
        }
        if (lane == 0) {
            float prev = first ? 0.f : g_skip[b * DD + oo];
            g_skip[b * DD + oo] = prev + accs + fc_b[oo];
            g_qadd[b * DD + oo] = accq;
        }
    }
}

// ---------------- tf32 tensor-core batched GEMM, cp.async pipelined --------
// R14 winner + BK=32 (launches full-size; NO chunking — R15 lesson):
// CTA tile 128x128x32, 4 warps, warp tile 64x64 via 4x8 m16n8k8
// (4 kk-halves/iter), 3 stages (107.5KB), 2 CTAs/SM.
// A-fragments via ldmatrix.m8n8.x4.b16 (stride 36: 144*r mod 128 = 16r,
// conflict-free). B scalar LDS, stride 136 (8k+c covers all banks).
// ADDQ: epilogue adds qadd[row] broadcast (f_in = Cin + qadd inline).
#define GSTAGES 3
#define AS_FLOATS 4608            /* 128*36 */
#define BS_FLOATS 4352            /* 32*136 */
#define STG_FLOATS (AS_FLOATS + BS_FLOATS)
#define GEMM_SMEM (GSTAGES * STG_FLOATS * 4)

__device__ __forceinline__ void cp16(unsigned dst, const float* src) {
    asm volatile("cp.async.cg.shared.global [%0], [%1], 16;" :: "r"(dst), "l"(src));
}

template<int M_, int K_, bool RELU, bool ADDIN, bool BIAS, bool TF32OUT, bool ADDQ>
__global__ void __launch_bounds__(128, 2)
gemm_tc(const float* __restrict__ A,
        const float* __restrict__ Bm,
        const float* __restrict__ bias,
        const float* __restrict__ Cin,
        float* __restrict__ C) {
    extern __shared__ float smem[];
    const int b  = blockIdx.z;
    const int m0 = blockIdx.y * 128;
    const int n0 = blockIdx.x * 128;
    const int tid  = threadIdx.x;
    const int warp = tid >> 5, lane = tid & 31;
    const int wm = (warp & 1) * 64;    // 0 or 64
    const int wn = (warp >> 1) * 64;   // 0 or 64
    const float* Bbase = Bm + (size_t)b * K_ * LL;

    // A stage-load: rows tid>>3 (+16h, h=0..7), cols (tid&7)*4
    const int ar = tid >> 3;
    const int ac = (tid & 7) * 4;
    // B stage-load: rows tid>>5 (+4h, h=0..7), cols (tid&31)*4
    const int bkr = tid >> 5;
    const int bcb = (tid & 31) * 4;

    const unsigned sbase = (unsigned)__cvta_generic_to_shared(smem);

    // ldmatrix per-thread source offset (floats, stride 36):
    //   matrix = lane>>3: bit0 -> +8 rows, bit1 -> +4 cols
    const int a_mat = lane >> 3;
    const int a_ld_off = (((a_mat & 1) * 8) + (lane & 7)) * 36 + (a_mat >> 1) * 4;

    float c[4][8][4];
    #pragma unroll
    for (int i = 0; i < 4; i++)
        #pragma unroll
        for (int j = 0; j < 8; j++)
            #pragma unroll
            for (int r = 0; r < 4; r++) c[i][j][r] = 0.f;

    const int nIter = K_ / 32;

    auto load_stage = [&](int it, int stg) {
        unsigned abase = sbase + (unsigned)(stg * STG_FLOATS) * 4u;
        unsigned bbase = abase + (unsigned)AS_FLOATS * 4u;
        int k0 = it * 32;
        #pragma unroll
        for (int h = 0; h < 8; h++) {
            int m = ar + h * 16;
            cp16(abase + (unsigned)(m * 36 + ac) * 4u,
                 &A[(size_t)(m0 + m) * K_ + k0 + ac]);
        }
        #pragma unroll
        for (int h = 0; h < 8; h++) {
            int k = bkr + h * 4;
            cp16(bbase + (unsigned)(k * 136 + bcb) * 4u,
                 &Bbase[(size_t)(k0 + k) * LL + n0 + bcb]);
        }
    };

    #pragma unroll
    for (int s = 0; s < GSTAGES - 1; s++) {
        load_stage(s, s);
        asm volatile("cp.async.commit_group;");
    }

    int cur = 0, nxt_stg = GSTAGES - 1;
    for (int i = 0; i < nIter; i++) {
        asm volatile("cp.async.wait_group %0;" :: "n"(GSTAGES - 2));
        __syncthreads();
        int nxt = i + GSTAGES - 1;
        if (nxt < nIter) load_stage(nxt, nxt_stg);
        asm volatile("cp.async.commit_group;");
        if (++nxt_stg == GSTAGES) nxt_stg = 0;

        const unsigned as_u = sbase + (unsigned)(cur * STG_FLOATS) * 4u;
        const float* bs_ = smem + cur * STG_FLOATS + AS_FLOATS;
        if (++cur == GSTAGES) cur = 0;

        #pragma unroll
        for (int kk = 0; kk < 32; kk += 8) {
            unsigned af[4][4], bf[8][2];
            #pragma unroll
            for (int mi = 0; mi < 4; mi++) {
                unsigned aaddr = as_u +
                    (unsigned)((wm + mi * 16) * 36 + kk + a_ld_off) * 4u;
                asm volatile(
                    "ldmatrix.sync.aligned.m8n8.x4.shared.b16 {%0,%1,%2,%3}, [%4];"
                    : "=r"(af[mi][0]), "=r"(af[mi][1]),
                      "=r"(af[mi][2]), "=r"(af[mi][3])
                    : "r"(aaddr));
            }
            #pragma unroll
            for (int ni = 0; ni < 8; ni++) {
                int col = wn + ni * 8 + (lane >> 2);
                int kr = kk + (lane & 3);
                bf[ni][0] = __float_as_uint(bs_[ kr      * 136 + col]);
                bf[ni][1] = __float_as_uint(bs_[(kr + 4) * 136 + col]);
            }
            #pragma unroll
            for (int mi = 0; mi < 4; mi++)
                #pragma unroll
                for (int ni = 0; ni < 8; ni++) {
                    asm volatile(
                        "mma.sync.aligned.m16n8k8.row.col.f32.tf32.tf32.f32 "
                        "{%0,%1,%2,%3}, {%4,%5,%6,%7}, {%8,%9}, {%0,%1,%2,%3};"
                        : "+f"(c[mi][ni][0]), "+f"(c[mi][ni][1]),
                          "+f"(c[mi][ni][2]), "+f"(c[mi][ni][3])
                        : "r"(af[mi][0]), "r"(af[mi][1]), "r"(af[mi][2]), "r"(af[mi][3]),
                          "r"(bf[ni][0]), "r"(bf[ni][1]));
                }
        }
    }

    // ---- epilogue
    const size_t base = (size_t)b * M_ * LL;
    const float* qa = ADDQ ? (g_qadd + b * DD) : nullptr;
    #pragma unroll
    for (int mi = 0; mi < 4; mi++) {
        int row = m0 + wm + mi * 16 + (lane >> 2);
        float bv0 = BIAS ? bias[row] : 0.f;
        float bv1 = BIAS ? bias[row + 8] : 0.f;
        if (ADDQ) { bv0 += qa[row]; bv1 += qa[row + 8]; }
        #pragma unroll
        for (int ni = 0; ni < 8; ni++) {
            int col = n0 + wn + ni * 8 + (lane & 3) * 2;
            float v0 = c[mi][ni][0] + bv0, v1 = c[mi][ni][1] + bv0;
            float v2 = c[mi][ni][2] + bv1, v3 = c[mi][ni][3] + bv1;
            if (RELU) {
                v0 = fmaxf(v0, 0.f); v1 = fmaxf(v1, 0.f);
                v2 = fmaxf(v2, 0.f); v3 = fmaxf(v3, 0.f);
            }
            size_t i0 = base + (size_t)row * LL + col;
            size_t i1 = base + (size_t)(row + 8) * LL + col;
            if (ADDIN) {
                float2 p0 = *(const float2*)&Cin[i0];
                float2 p1 = *(const float2*)&Cin[i1];
                v0 += p0.x; v1 += p0.y; v2 += p1.x; v3 += p1.y;
            }
            if (TF32OUT) {
                v0 = tf32r(v0); v1 = tf32r(v1);
                v2 = tf32r(v2); v3 = tf32r(v3);
            }
            *(float2*)&C[i0] = make_float2(v0, v1);
            *(float2*)&C[i1] = make_float2(v2, v3);
        }
    }
}

// ---------------- final relu + BatchNorm over batch -> out -----------------
__global__ void bn_kernel(float* __restrict__ out) {
    int d = blockIdx.x;        // 0..255
    int b = threadIdx.x;       // 0..63
    __shared__ float r1[64], r2[64];
    float y = fmaxf(g_skip[b * DD + d], 0.f);
    r1[b] = y; r2[b] = y * y;
    __syncthreads();
    for (int o = 32; o > 0; o >>= 1) {
        if (b < o) { r1[b] += r1[b + o]; r2[b] += r2[b + o]; }
        __syncthreads();
    }
    float mu = r1[0] * (1.f / 64.f);
    float var = r2[0] * (1.f / 64.f) - mu * mu;
    float rs = rsqrtf(var + 1e-5f);
    out[b * DD + d] = (y - mu) * rs;
}

// ---------------- launch ----------------
extern "C" void kernel_launch(void* const* d_in, const int* in_sizes, int n_in,
                              void* d_out, int out_size) {
    const float* x      = (const float*)d_in[0];
    const float* wk     = (const float*)d_in[1];
    const float* wq     = (const float*)d_in[2];
    const float* fcq_w  = (const float*)d_in[3];
    const float* fc_w   = (const float*)d_in[4];
    const float* fc_b   = (const float*)d_in[5];
    const float* att_g  = (const float*)d_in[6];
    const float* att_b  = (const float*)d_in[7];
    const float* w1     = (const float*)d_in[8];
    const float* b1     = (const float*)d_in[9];
    const float* w2     = (const float*)d_in[10];
    const float* b2     = (const float*)d_in[11];
    const float* ffw_g  = (const float*)d_in[12];
    const float* ffw_b  = (const float*)d_in[13];
    float* out = (float*)d_out;

    float *p_v, *p_h, *p_h1, *p_w1, *p_w2;
    cudaGetSymbolAddress((void**)&p_v,  g_v);
    cudaGetSymbolAddress((void**)&p_h,  g_h);
    cudaGetSymbolAddress((void**)&p_h1, g_h1);
    cudaGetSymbolAddress((void**)&p_w1, g_w1);
    cudaGetSymbolAddress((void**)&p_w2, g_w2);

    cudaFuncSetAttribute(gemm_tc<HH, DD, true, false, true, true, false>,
                         cudaFuncAttributeMaxDynamicSharedMemorySize, GEMM_SMEM);
    cudaFuncSetAttribute(gemm_tc<DD, HH, false, true, true, false, true>,
                         cudaFuncAttributeMaxDynamicSharedMemorySize, GEMM_SMEM);

    prep_kernel<<<512, 256>>>(w1, w2);

    for (int i = 0; i < 2; i++) {
        const float* vsrc = (i == 0) ? x : (const float*)p_v;
        att_ln_kernel<<<BB * LL / 256, 256>>>(vsrc, att_g + i * DD, att_b + i * DD);
        colstats_kernel<<<BB * DD, 256>>>();
        q_kernel<<<dim3(BB, 8), 512>>>(wq + (size_t)i * KC * 2 * DD);
        qk_kernel<<<dim3(BB, 2), 128>>>(wk + (size_t)i * KC * DD);
        score_kernel<<<dim3(BB, LL / 256), 256>>>();
        softmax_fin<<<BB, 1024>>>();
        att_kernel<<<BB * DD, 256>>>();
        skip_kernel<<<dim3(BB, 4), 256>>>(fc_w + (size_t)i * DD * 2 * DD,
                                          fc_b + (size_t)i * DD,
                                          fcq_w + (size_t)i * DD * DD, i == 0);
        ffn_ln_kernel<<<BB * LL / 256, 256>>>(vsrc, ffw_g + i * DD, ffw_b + i * DD);
        // h1 = relu(w1 @ h + b1) : (512 x 2048) per batch, tf32-rounded store
        gemm_tc<HH, DD, true, false, true, true, false>
            <<<dim3(LL / 128, HH / 128, BB), 128, GEMM_SMEM>>>(
                p_w1 + (size_t)i * HH * DD, p_h,
                b1 + (size_t)i * HH, nullptr, p_h1);
        // v = w2 @ h1 + b2 + (vsrc + qadd) : (256 x 2048) per batch -> g_v
        gemm_tc<DD, HH, false, true, true, false, true>
            <<<dim3(LL / 128, DD / 128, BB), 128, GEMM_SMEM>>>(
                p_w2 + (size_t)i * DD * HH, p_h1,
                b2 + (size_t)i * DD, vsrc, p_v);
    }

    bn_kernel<<<DD, 64>>>(out);
}